// round 12
// baseline (speedup 1.0000x reference)
#include <cuda_runtime.h>
#include <cuda_bf16.h>
#include <math.h>
#include <cstdint>

// Shapes fixed by the problem
#define NN     1024
#define LL     30
#define KK     32      // padded latent (4 k-steps of 8)
#define GG     10000
#define NBATCH 64
#define NT     256     // threads per block (8 warps)
#define GT     256     // genes per block (32 per warp = 4 n-tiles of 8)
#define CH     16      // cells per chunk = MMA M
#define CSTRIDE 33     // padded C row stride (floats)

__device__ __forceinline__ float to_tf32(float x) {
    float r; asm("cvt.rna.tf32.f32 %0, %1;" : "=f"(r) : "f"(x)); return r;
}
__device__ __forceinline__ float softplus_fast(float x) {
    return fmaxf(x, 0.f) + __logf(1.f + __expf(-fabsf(x)));
}

// mma.sync m16n8k8 tf32: D[16x8] += A[16x8] * B[8x8]   (A row-major, B col-major)
// Fragment mapping (gid = lane>>2, tig = lane&3):
//   A: a0=(gid,tig) a1=(gid+8,tig) a2=(gid,tig+4) a3=(gid+8,tig+4)
//   B: b0=(k=tig,n=gid) b1=(k=tig+4,n=gid)
//   D: d0=(gid,2tig) d1=(gid,2tig+1) d2=(gid+8,2tig) d3=(gid+8,2tig+1)
#define MMA_TF32(d0,d1,d2,d3, a0,a1,a2,a3, b0,b1) \
    asm volatile("mma.sync.aligned.m16n8k8.row.col.f32.tf32.tf32.f32 " \
        "{%0,%1,%2,%3}, {%4,%5,%6,%7}, {%8,%9}, {%0,%1,%2,%3};" \
        : "+f"(d0), "+f"(d1), "+f"(d2), "+f"(d3) \
        : "r"(a0), "r"(a1), "r"(a2), "r"(a3), "r"(b0), "r"(b1))

// ---------------------------------------------------------------------------
// Warp-MMA decoder. Grid = (ceil(G/256), NB). Block (gx, b):
//   - builds cell list of batch b in shared
//   - folds C[k][g] = A_emb[b,g,k] + W[k,g] (tf32) into shared, once
//   - each warp keeps B-fragments for its 32 genes in registers (persistent)
//   - per 16-cell chunk: z staged fragment-ordered (1 LDS.128 per k-step),
//     16 MMAs/warp produce D[16 cells x 32 genes], softplus epilogue with
//     float2 stores (consecutive genes) -> full-sector STG
//   - b==0 plane emits exp(px_r) tail
// ---------------------------------------------------------------------------
__global__ __launch_bounds__(NT, 2)
void decoder_kernel(const float* __restrict__ z,
                    const int*   __restrict__ bc,
                    const float* __restrict__ sf,
                    const float* __restrict__ W,
                    const float* __restrict__ A,
                    const float* __restrict__ bemb,
                    const float* __restrict__ px_r,
                    float* __restrict__ out) {
    __shared__ float Csh[GT * CSTRIDE];          // 33792 B
    __shared__ __align__(16) uint32_t zf[4 * 32 * 4];  // 2048 B, fragment-ordered z
    __shared__ int   lsh[NN];                    // 4096 B
    __shared__ float sfsh[CH];
    __shared__ int   cnt;

    const int tid  = threadIdx.x;
    const int wid  = tid >> 5;
    const int lane = tid & 31;
    const int gid  = lane >> 2;    // 0..7
    const int tig  = lane & 3;     // 0..3
    const int b    = blockIdx.y;
    const int g0   = blockIdx.x * GT;

    if (tid == 0) cnt = 0;
    // exp(px_r) tail on the b==0 plane (grid.x*NT = 10240 covers GG)
    if (b == 0) {
        int i = blockIdx.x * NT + tid;
        if (i < GG) out[(size_t)NN * GG + i] = __expf(px_r[i]);
    }
    __syncthreads();

    // Build this batch's cell list (order irrelevant; each cell owns its row)
    for (int i = tid; i < NN; i += NT)
        if (bc[i] == b) { int p = atomicAdd(&cnt, 1); lsh[p] = i; }

    // Fold C: one gene per thread. Csh[g_local*33 + k] = tf32(A[b,g,k] + W[k,g])
    {
        const int g = g0 + tid;
        if (g < GG) {
            const float* Arow = A + ((size_t)b * GG + g) * LL;
#pragma unroll
            for (int l = 0; l < LL; l++)
                Csh[tid * CSTRIDE + l] = to_tf32(Arow[l] + W[l * GG + g]);
            Csh[tid * CSTRIDE + 30] = 0.f;
            Csh[tid * CSTRIDE + 31] = 0.f;
        } else {
#pragma unroll
            for (int l = 0; l < KK; l++) Csh[tid * CSTRIDE + l] = 0.f;
        }
    }
    __syncthreads();
    const int e = cnt;

    // Extract persistent B-fragments: warp genes = g0 + wid*32 + nt*8 + n
    uint32_t Bf[4][4][2];                 // [ntile][kstep][b0,b1]
#pragma unroll
    for (int nt = 0; nt < 4; nt++) {
        const int gl = wid * 32 + nt * 8 + gid;   // block-local gene of this lane
#pragma unroll
        for (int ks = 0; ks < 4; ks++) {
            Bf[nt][ks][0] = __float_as_uint(Csh[gl * CSTRIDE + ks * 8 + tig]);
            Bf[nt][ks][1] = __float_as_uint(Csh[gl * CSTRIDE + ks * 8 + tig + 4]);
        }
    }
    // Bias for this thread's D-fragment genes (2tig, 2tig+1 per n-tile)
    float bbr[4][2];
#pragma unroll
    for (int nt = 0; nt < 4; nt++) {
#pragma unroll
        for (int h = 0; h < 2; h++) {
            int gene = g0 + wid * 32 + nt * 8 + 2 * tig + h;
            bbr[nt][h] = (gene < GG) ? bemb[(size_t)b * GG + gene] : 0.f;
        }
    }

    for (int c0 = 0; c0 < e; c0 += CH) {
        const int nch = min(CH, e - c0);
        __syncthreads();   // zf/sfsh reuse safety
        // Stage z fragment-ordered: zf[(ks*32+ln)*4 + j] = A-frag reg j of lane ln
        // j: row = (ln>>2) + ((j&1)<<3), col = (ln&3) + ((j>>1)<<2) + ks*8
        for (int i = tid; i < 512; i += NT) {
            int ks = i >> 7, r = i & 127, ln = r >> 2, j = r & 3;
            int row = (ln >> 2) + ((j & 1) << 3);
            int col = (ln & 3) + ((j >> 1) << 2) + ks * 8;
            float v = 0.f;
            if (row < nch && col < LL) v = to_tf32(z[lsh[c0 + row] * LL + col]);
            zf[i] = __float_as_uint(v);
        }
        if (tid < CH) sfsh[tid] = (tid < nch) ? sf[lsh[c0 + tid]] : 0.f;
        __syncthreads();

        // Load A-fragments: one LDS.128 per k-step
        uint4 za[4];
#pragma unroll
        for (int ks = 0; ks < 4; ks++)
            za[ks] = *(const uint4*)&zf[(ks * 32 + lane) * 4];

        const float sf0 = sfsh[gid];
        const float sf1 = sfsh[gid + 8];
        const bool  c0ok = (gid < nch);
        const bool  c1ok = (gid + 8 < nch);
        const size_t row0 = c0ok ? (size_t)lsh[c0 + gid] * GG : 0;
        const size_t row1 = c1ok ? (size_t)lsh[c0 + gid + 8] * GG : 0;

#pragma unroll
        for (int nt = 0; nt < 4; nt++) {
            float d0 = 0.f, d1 = 0.f, d2 = 0.f, d3 = 0.f;
#pragma unroll
            for (int ks = 0; ks < 4; ks++)
                MMA_TF32(d0, d1, d2, d3,
                         za[ks].x, za[ks].y, za[ks].z, za[ks].w,
                         Bf[nt][ks][0], Bf[nt][ks][1]);

            const int gene = g0 + wid * 32 + nt * 8 + 2 * tig;  // even; gene+1<GG iff gene<GG
            if (gene < GG) {
                if (c0ok) {
                    float2 v;
                    v.x = softplus_fast(d0 + bbr[nt][0]) * sf0;
                    v.y = softplus_fast(d1 + bbr[nt][1]) * sf0;
                    *(float2*)&out[row0 + gene] = v;
                }
                if (c1ok) {
                    float2 v;
                    v.x = softplus_fast(d2 + bbr[nt][0]) * sf1;
                    v.y = softplus_fast(d3 + bbr[nt][1]) * sf1;
                    *(float2*)&out[row1 + gene] = v;
                }
            }
        }
    }
}

// ---------------------------------------------------------------------------
// Launch. Inputs per metadata order:
//   0: z [N,L] f32        1: batch_covariate [N] i32   2: size_factor [N,1] f32
//   3: W_amat [L,G] f32   4: A_emb [NB,G,L] f32        5: b_emb [NB,G] f32
//   6: px_r [G] f32
// Output: mean [N,G] f32 followed by inverse_dispersion [G] f32.
// ---------------------------------------------------------------------------
extern "C" void kernel_launch(void* const* d_in, const int* in_sizes, int n_in,
                              void* d_out, int out_size) {
    const float* z    = (const float*)d_in[0];
    const int*   bc   = (const int*)  d_in[1];
    const float* sf   = (const float*)d_in[2];
    const float* W    = (const float*)d_in[3];
    const float* A    = (const float*)d_in[4];
    const float* bemb = (const float*)d_in[5];
    const float* pxr  = (const float*)d_in[6];
    float* out = (float*)d_out;

    dim3 grid((GG + GT - 1) / GT, NBATCH);
    decoder_kernel<<<grid, NT>>>(z, bc, sf, W, A, bemb, pxr, out);
}

// round 13
// speedup vs baseline: 1.4359x; 1.4359x over previous
#include <cuda_runtime.h>
#include <cuda_bf16.h>
#include <math.h>
#include <cstdint>

// Shapes fixed by the problem
#define NN     1024
#define LL     30
#define GG     10000
#define NBATCH 64
#define NT     256     // threads per block
#define GT     256     // genes per block (2 per lane-pair)
#define GH     128     // gene stride between a pair's two genes
#define CH     16      // cells per chunk staged in shared

typedef unsigned long long u64;

// ---- packed f32x2 helpers (sm_103a) ---------------------------------------
#define FMA2(d, a, b, c) \
    asm("fma.rn.f32x2 %0, %1, %2, %3;" : "=l"(d) : "l"(a), "l"(b), "l"(c))
#define ADD2(d, a, b) \
    asm("add.rn.f32x2 %0, %1, %2;" : "=l"(d) : "l"(a), "l"(b))
#define PACK2(d, lo, hi) \
    asm("mov.b64 %0, {%1, %2};" : "=l"(d) : "f"(lo), "f"(hi))
#define UNPACK2(lo, hi, s) \
    asm("mov.b64 {%0, %1}, %2;" : "=f"(lo), "=f"(hi) : "l"(s))

__device__ __forceinline__ float softplus_fast(float x) {
    return fmaxf(x, 0.f) + __logf(1.f + __expf(-fabsf(x)));
}

// ---------------------------------------------------------------------------
// Split-K lane-pair decoder. Grid = (40, 64), 256 threads.
// Lane pair (2t, 2t+1) owns genes gA = g0 + (tid>>1) and gB = gA + 128;
// even lane holds K-half 0..15, odd lane K-half 16..31 (k30,31 zero pads).
// Per cell: each lane does 4 LDS.128 (its K-half of z) + 16 FMA2 (2 genes),
// two shfl.bfly combine the halves on BOTH lanes, then even lane emits gene
// gA and odd lane emits gene gB -> every lane does exactly one softplus+STG.
// C-registers halve vs 2-gene blocking -> 64-reg budget -> 4 blocks/SM.
// ---------------------------------------------------------------------------
__global__ __launch_bounds__(NT, 4)
void decoder_kernel(const float* __restrict__ z,
                    const int*   __restrict__ bc,
                    const float* __restrict__ sf,
                    const float* __restrict__ W,
                    const float* __restrict__ A,
                    const float* __restrict__ bemb,
                    const float* __restrict__ px_r,
                    float* __restrict__ out) {
    __shared__ __align__(16) float zsh[CH * 32];   // 2048 B
    __shared__ float sfsh[CH];
    __shared__ int   lsh[NN];                      // cell ids of this batch
    __shared__ int   cnt;

    const int tid = threadIdx.x;
    const int h   = tid & 1;          // K-half: 0 -> k0..15, 1 -> k16..31
    const int gl  = tid >> 1;         // 0..127: pair index = local gene
    const int b   = blockIdx.y;
    const int g0  = blockIdx.x * GT;

    const int gA = g0 + gl;
    const int gB = gA + GH;
    const int myg = h ? gB : gA;      // gene this lane's epilogue emits

    if (tid == 0) cnt = 0;
    // exp(px_r) tail on the b==0 plane (40*256 = 10240 covers GG)
    if (b == 0) {
        int i = blockIdx.x * NT + tid;
        if (i < GG) out[(size_t)NN * GG + i] = __expf(px_r[i]);
    }
    __syncthreads();

    // Build this batch's cell list (order irrelevant; each cell owns its row)
    for (int i = tid; i < NN; i += NT)
        if (bc[i] == b) { int p = atomicAdd(&cnt, 1); lsh[p] = i; }

    // Fold this lane's K-half of C = A[b,g,:] + W[:,g] for both genes.
    // h=0: A-row pairs 0..7 (bytes 0..63); h=1: pairs 8..14 + zero pad pair.
    u64 CA[8], CB[8];
    const int k0 = h * 16;
    const int np = h ? 7 : 8;
    if (gA < GG) {
        const u64* Ar = (const u64*)(A + ((size_t)b * GG + gA) * LL) + h * 8;
#pragma unroll
        for (int q = 0; q < 8; q++) {
            if (q < np) {
                u64 w2;
                PACK2(w2, W[(k0 + 2 * q) * GG + gA], W[(k0 + 2 * q + 1) * GG + gA]);
                ADD2(CA[q], Ar[q], w2);
            } else CA[q] = 0ULL;
        }
    } else {
#pragma unroll
        for (int q = 0; q < 8; q++) CA[q] = 0ULL;
    }
    if (gB < GG) {
        const u64* Ar = (const u64*)(A + ((size_t)b * GG + gB) * LL) + h * 8;
#pragma unroll
        for (int q = 0; q < 8; q++) {
            if (q < np) {
                u64 w2;
                PACK2(w2, W[(k0 + 2 * q) * GG + gB], W[(k0 + 2 * q + 1) * GG + gB]);
                ADD2(CB[q], Ar[q], w2);
            } else CB[q] = 0ULL;
        }
    } else {
#pragma unroll
        for (int q = 0; q < 8; q++) CB[q] = 0ULL;
    }
    const float mybb = (myg < GG) ? bemb[(size_t)b * GG + myg] : 0.f;

    __syncthreads();
    const int e = cnt;

    for (int c0 = 0; c0 < e; c0 += CH) {
        const int nch = min(CH, e - c0);
        __syncthreads();   // zsh reuse safety
        // stage z rows: stride 32 floats, pads zeroed (k >= LL)
        for (int i = tid; i < CH * 32; i += NT) {
            int j = i >> 5, l = i & 31;
            zsh[i] = (l < LL && j < nch) ? z[lsh[c0 + j] * LL + l] : 0.f;
        }
        if (tid < CH) sfsh[tid] = (tid < nch) ? sf[lsh[c0 + tid]] : 0.f;
        __syncthreads();

        for (int j = 0; j < nch; j++) {
            // this lane's K-half of cell j: 16 floats = 4 LDS.128
            const ulonglong2* zp = (const ulonglong2*)(zsh + j * 32 + h * 16);
            ulonglong2 v0 = zp[0], v1 = zp[1], v2 = zp[2], v3 = zp[3];
            u64 aA = 0ULL, aB = 0ULL;
            FMA2(aA, CA[0], v0.x, aA);  FMA2(aB, CB[0], v0.x, aB);
            FMA2(aA, CA[1], v0.y, aA);  FMA2(aB, CB[1], v0.y, aB);
            FMA2(aA, CA[2], v1.x, aA);  FMA2(aB, CB[2], v1.x, aB);
            FMA2(aA, CA[3], v1.y, aA);  FMA2(aB, CB[3], v1.y, aB);
            FMA2(aA, CA[4], v2.x, aA);  FMA2(aB, CB[4], v2.x, aB);
            FMA2(aA, CA[5], v2.y, aA);  FMA2(aB, CB[5], v2.y, aB);
            FMA2(aA, CA[6], v3.x, aA);  FMA2(aB, CB[6], v3.x, aB);
            FMA2(aA, CA[7], v3.y, aA);  FMA2(aB, CB[7], v3.y, aB);

            float xA, yA, xB, yB;
            UNPACK2(xA, yA, aA);
            UNPACK2(xB, yB, aB);
            float fA = xA + yA;
            float fB = xB + yB;
            // combine K-halves across the lane pair (both lanes get full sums)
            fA += __shfl_xor_sync(0xffffffffu, fA, 1);
            fB += __shfl_xor_sync(0xffffffffu, fB, 1);

            float acc = (h ? fB : fA) + mybb;
            if (myg < GG)
                out[(size_t)lsh[c0 + j] * GG + myg] = softplus_fast(acc) * sfsh[j];
        }
    }
}

// ---------------------------------------------------------------------------
// Launch. Inputs per metadata order:
//   0: z [N,L] f32        1: batch_covariate [N] i32   2: size_factor [N,1] f32
//   3: W_amat [L,G] f32   4: A_emb [NB,G,L] f32        5: b_emb [NB,G] f32
//   6: px_r [G] f32
// Output: mean [N,G] f32 followed by inverse_dispersion [G] f32.
// ---------------------------------------------------------------------------
extern "C" void kernel_launch(void* const* d_in, const int* in_sizes, int n_in,
                              void* d_out, int out_size) {
    const float* z    = (const float*)d_in[0];
    const int*   bc   = (const int*)  d_in[1];
    const float* sf   = (const float*)d_in[2];
    const float* W    = (const float*)d_in[3];
    const float* A    = (const float*)d_in[4];
    const float* bemb = (const float*)d_in[5];
    const float* pxr  = (const float*)d_in[6];
    float* out = (float*)d_out;

    dim3 grid((GG + GT - 1) / GT, NBATCH);
    decoder_kernel<<<grid, NT>>>(z, bc, sf, W, A, bemb, pxr, out);
}

// round 14
// speedup vs baseline: 1.5235x; 1.0610x over previous
#include <cuda_runtime.h>
#include <cuda_bf16.h>
#include <math.h>
#include <cstdint>

// Shapes fixed by the problem
#define NN     1024
#define LL     30
#define GG     10000
#define NBATCH 64
#define NT     256     // threads per block
#define GT     256     // genes per block (2 per lane-pair)
#define GH     128     // gene stride between a pair's two genes
#define CH     16      // cells per chunk staged in shared

typedef unsigned long long u64;

// ---- packed f32x2 helpers (sm_103a) ---------------------------------------
#define FMA2(d, a, b, c) \
    asm("fma.rn.f32x2 %0, %1, %2, %3;" : "=l"(d) : "l"(a), "l"(b), "l"(c))
#define ADD2(d, a, b) \
    asm("add.rn.f32x2 %0, %1, %2;" : "=l"(d) : "l"(a), "l"(b))
#define PACK2(d, lo, hi) \
    asm("mov.b64 %0, {%1, %2};" : "=l"(d) : "f"(lo), "f"(hi))
#define UNPACK2(lo, hi, s) \
    asm("mov.b64 {%0, %1}, %2;" : "=f"(lo), "=f"(hi) : "l"(s))

__device__ __forceinline__ float softplus_fast(float x) {
    return fmaxf(x, 0.f) + __logf(1.f + __expf(-fabsf(x)));
}

// ---------------------------------------------------------------------------
// Split-K lane-pair decoder, 2-cell interleaved inner loop, single-shfl
// exchange. Lane pair (2t, 2t+1) owns genes gA = g0 + (tid>>1), gB = gA+128;
// even lane holds K 0..15, odd lane K 16..31 (zeros at 30,31). Per cell each
// lane computes its K-half partials for BOTH genes, then the pair does ONE
// shfl: each lane sends the partial the other lane's gene needs and keeps
// its own -> every lane finishes exactly one (cell, gene) with softplus+STG.
// Cells processed two at a time with independent chains for ILP.
// ---------------------------------------------------------------------------
__global__ __launch_bounds__(NT, 4)
void decoder_kernel(const float* __restrict__ z,
                    const int*   __restrict__ bc,
                    const float* __restrict__ sf,
                    const float* __restrict__ W,
                    const float* __restrict__ A,
                    const float* __restrict__ bemb,
                    const float* __restrict__ px_r,
                    float* __restrict__ out) {
    __shared__ __align__(16) float zsh[CH * 32];   // 2048 B
    __shared__ float sfsh[CH];
    __shared__ int   lsh[NN];
    __shared__ int   cnt;

    const int tid = threadIdx.x;
    const int h   = tid & 1;          // K-half selector
    const int gl  = tid >> 1;
    const int b   = blockIdx.y;
    const int g0  = blockIdx.x * GT;

    const int gA  = g0 + gl;
    const int gB  = gA + GH;
    const int myg = h ? gB : gA;      // gene this lane emits

    if (tid == 0) cnt = 0;
    if (b == 0) {                     // exp(px_r) tail on b==0 plane
        int i = blockIdx.x * NT + tid;
        if (i < GG) out[(size_t)NN * GG + i] = __expf(px_r[i]);
    }
    __syncthreads();

    for (int i = tid; i < NN; i += NT)
        if (bc[i] == b) { int p = atomicAdd(&cnt, 1); lsh[p] = i; }

    // Fold this lane's K-half of C = A[b,g,:] + W[:,g] for both genes.
    u64 CA[8], CB[8];
    const int k0 = h * 16;
    const int np = h ? 7 : 8;         // odd half: 7 real pairs + zero pad
    if (gA < GG) {
        const u64* Ar = (const u64*)(A + ((size_t)b * GG + gA) * LL) + h * 8;
#pragma unroll
        for (int q = 0; q < 8; q++) {
            if (q < np) {
                u64 w2;
                PACK2(w2, W[(k0 + 2 * q) * GG + gA], W[(k0 + 2 * q + 1) * GG + gA]);
                ADD2(CA[q], Ar[q], w2);
            } else CA[q] = 0ULL;
        }
    } else {
#pragma unroll
        for (int q = 0; q < 8; q++) CA[q] = 0ULL;
    }
    if (gB < GG) {
        const u64* Ar = (const u64*)(A + ((size_t)b * GG + gB) * LL) + h * 8;
#pragma unroll
        for (int q = 0; q < 8; q++) {
            if (q < np) {
                u64 w2;
                PACK2(w2, W[(k0 + 2 * q) * GG + gB], W[(k0 + 2 * q + 1) * GG + gB]);
                ADD2(CB[q], Ar[q], w2);
            } else CB[q] = 0ULL;
        }
    } else {
#pragma unroll
        for (int q = 0; q < 8; q++) CB[q] = 0ULL;
    }
    const float mybb = (myg < GG) ? bemb[(size_t)b * GG + myg] : 0.f;
    const bool  emit = (myg < GG);

    __syncthreads();
    const int e = cnt;

    for (int c0 = 0; c0 < e; c0 += CH) {
        const int nch = min(CH, e - c0);
        __syncthreads();
        for (int i = tid; i < CH * 32; i += NT) {
            int j = i >> 5, l = i & 31;
            zsh[i] = (l < LL && j < nch) ? z[lsh[c0 + j] * LL + l] : 0.f;
        }
        if (tid < CH) sfsh[tid] = (tid < nch) ? sf[lsh[c0 + tid]] : 0.f;
        __syncthreads();

        int j = 0;
        // ---- 2-cell interleaved main loop --------------------------------
        for (; j + 2 <= nch; j += 2) {
            const ulonglong2* zp0 = (const ulonglong2*)(zsh + (j    ) * 32 + h * 16);
            const ulonglong2* zp1 = (const ulonglong2*)(zsh + (j + 1) * 32 + h * 16);
            ulonglong2 p0 = zp0[0], p1 = zp0[1], p2 = zp0[2], p3 = zp0[3];
            ulonglong2 q0 = zp1[0], q1 = zp1[1], q2 = zp1[2], q3 = zp1[3];

            u64 aA0 = 0ULL, aB0 = 0ULL, aA1 = 0ULL, aB1 = 0ULL;
            FMA2(aA0, CA[0], p0.x, aA0);  FMA2(aA1, CA[0], q0.x, aA1);
            FMA2(aB0, CB[0], p0.x, aB0);  FMA2(aB1, CB[0], q0.x, aB1);
            FMA2(aA0, CA[1], p0.y, aA0);  FMA2(aA1, CA[1], q0.y, aA1);
            FMA2(aB0, CB[1], p0.y, aB0);  FMA2(aB1, CB[1], q0.y, aB1);
            FMA2(aA0, CA[2], p1.x, aA0);  FMA2(aA1, CA[2], q1.x, aA1);
            FMA2(aB0, CB[2], p1.x, aB0);  FMA2(aB1, CB[2], q1.x, aB1);
            FMA2(aA0, CA[3], p1.y, aA0);  FMA2(aA1, CA[3], q1.y, aA1);
            FMA2(aB0, CB[3], p1.y, aB0);  FMA2(aB1, CB[3], q1.y, aB1);
            FMA2(aA0, CA[4], p2.x, aA0);  FMA2(aA1, CA[4], q2.x, aA1);
            FMA2(aB0, CB[4], p2.x, aB0);  FMA2(aB1, CB[4], q2.x, aB1);
            FMA2(aA0, CA[5], p2.y, aA0);  FMA2(aA1, CA[5], q2.y, aA1);
            FMA2(aB0, CB[5], p2.y, aB0);  FMA2(aB1, CB[5], q2.y, aB1);
            FMA2(aA0, CA[6], p3.x, aA0);  FMA2(aA1, CA[6], q3.x, aA1);
            FMA2(aB0, CB[6], p3.x, aB0);  FMA2(aB1, CB[6], q3.x, aB1);
            FMA2(aA0, CA[7], p3.y, aA0);  FMA2(aA1, CA[7], q3.y, aA1);
            FMA2(aB0, CB[7], p3.y, aB0);  FMA2(aB1, CB[7], q3.y, aB1);

            float xA, yA, xB, yB;
            UNPACK2(xA, yA, aA0);  UNPACK2(xB, yB, aB0);
            float fA0 = xA + yA, fB0 = xB + yB;
            UNPACK2(xA, yA, aA1);  UNPACK2(xB, yB, aB1);
            float fA1 = xA + yA, fB1 = xB + yB;

            // single exchange per cell: send what the partner's gene needs
            float keep0 = h ? fB0 : fA0, send0 = h ? fA0 : fB0;
            float keep1 = h ? fB1 : fA1, send1 = h ? fA1 : fB1;
            float recv0 = __shfl_xor_sync(0xffffffffu, send0, 1);
            float recv1 = __shfl_xor_sync(0xffffffffu, send1, 1);

            if (emit) {
                float acc0 = keep0 + recv0 + mybb;
                float acc1 = keep1 + recv1 + mybb;
                out[(size_t)lsh[c0 + j]     * GG + myg] = softplus_fast(acc0) * sfsh[j];
                out[(size_t)lsh[c0 + j + 1] * GG + myg] = softplus_fast(acc1) * sfsh[j + 1];
            }
        }
        // ---- tail (single cell) ------------------------------------------
        for (; j < nch; j++) {
            const ulonglong2* zp = (const ulonglong2*)(zsh + j * 32 + h * 16);
            ulonglong2 v0 = zp[0], v1 = zp[1], v2 = zp[2], v3 = zp[3];
            u64 aA = 0ULL, aB = 0ULL;
            FMA2(aA, CA[0], v0.x, aA);  FMA2(aB, CB[0], v0.x, aB);
            FMA2(aA, CA[1], v0.y, aA);  FMA2(aB, CB[1], v0.y, aB);
            FMA2(aA, CA[2], v1.x, aA);  FMA2(aB, CB[2], v1.x, aB);
            FMA2(aA, CA[3], v1.y, aA);  FMA2(aB, CB[3], v1.y, aB);
            FMA2(aA, CA[4], v2.x, aA);  FMA2(aB, CB[4], v2.x, aB);
            FMA2(aA, CA[5], v2.y, aA);  FMA2(aB, CB[5], v2.y, aB);
            FMA2(aA, CA[6], v3.x, aA);  FMA2(aB, CB[6], v3.x, aB);
            FMA2(aA, CA[7], v3.y, aA);  FMA2(aB, CB[7], v3.y, aB);

            float xA, yA, xB, yB;
            UNPACK2(xA, yA, aA);  UNPACK2(xB, yB, aB);
            float fA = xA + yA, fB = xB + yB;
            float keep = h ? fB : fA, send = h ? fA : fB;
            float recv = __shfl_xor_sync(0xffffffffu, send, 1);
            if (emit) {
                float acc = keep + recv + mybb;
                out[(size_t)lsh[c0 + j] * GG + myg] = softplus_fast(acc) * sfsh[j];
            }
        }
    }
}

// ---------------------------------------------------------------------------
// Launch. Inputs per metadata order:
//   0: z [N,L] f32        1: batch_covariate [N] i32   2: size_factor [N,1] f32
//   3: W_amat [L,G] f32   4: A_emb [NB,G,L] f32        5: b_emb [NB,G] f32
//   6: px_r [G] f32
// Output: mean [N,G] f32 followed by inverse_dispersion [G] f32.
// ---------------------------------------------------------------------------
extern "C" void kernel_launch(void* const* d_in, const int* in_sizes, int n_in,
                              void* d_out, int out_size) {
    const float* z    = (const float*)d_in[0];
    const int*   bc   = (const int*)  d_in[1];
    const float* sf   = (const float*)d_in[2];
    const float* W    = (const float*)d_in[3];
    const float* A    = (const float*)d_in[4];
    const float* bemb = (const float*)d_in[5];
    const float* pxr  = (const float*)d_in[6];
    float* out = (float*)d_out;

    dim3 grid((GG + GT - 1) / GT, NBATCH);
    decoder_kernel<<<grid, NT>>>(z, bc, sf, W, A, bemb, pxr, out);
}